// round 4
// baseline (speedup 1.0000x reference)
#include <cuda_runtime.h>
#include <cuda_bf16.h>
#include <cstdint>

// NT-Xent fused: N=4096, Z=128, T=0.5
#define TWO_N 8192
#define ZD 128
#define INV_T 2.0f
#define EXP_SCALE 2.8853900817779268f   // INV_T * log2(e)

#define BM 128
#define BN 128
#define ROW_TILES (TWO_N / BM)                       // 64
#define NUM_TILES (ROW_TILES * (ROW_TILES + 1) / 2)  // 2080 (upper triangle)
#define STRIDE 136                       // bf16 elems per smem row (128 + 8 pad)
#define SMEM_SZ (2 * BM * STRIDE * 2)    // 69632 bytes

// Scratch (device globals — no allocation allowed)
__device__ __nv_bfloat16 g_nrep_bf16[TWO_N * ZD];
__device__ float         g_rowsum  [TWO_N];
__device__ float         g_pos     [TWO_N];
__device__ float         g_scalar;
__device__ unsigned int  g_ticket;

// ---------------------------------------------------------------------------
// Kernel 1: row-normalize reps = concat(z1, z2) -> bf16; fp32 positives;
// zero rowsum; init ticket. One block per row, 128 threads.
// ---------------------------------------------------------------------------
__global__ void normalize_pos_kernel(const float* __restrict__ z1,
                                     const float* __restrict__ z2) {
    int row = blockIdx.x;
    int t = threadIdx.x;
    int peer = (row + TWO_N / 2) & (TWO_N - 1);
    const float* srcR = (row  < TWO_N / 2) ? (z1 + (size_t)row * ZD)
                                           : (z2 + (size_t)(row  - TWO_N / 2) * ZD);
    const float* srcP = (peer < TWO_N / 2) ? (z1 + (size_t)peer * ZD)
                                           : (z2 + (size_t)(peer - TWO_N / 2) * ZD);
    float v = srcR[t];
    float p = srcP[t];
    float s0 = v * v, s1 = p * p, s2 = v * p;
    #pragma unroll
    for (int o = 16; o > 0; o >>= 1) {
        s0 += __shfl_xor_sync(0xFFFFFFFFu, s0, o);
        s1 += __shfl_xor_sync(0xFFFFFFFFu, s1, o);
        s2 += __shfl_xor_sync(0xFFFFFFFFu, s2, o);
    }
    __shared__ float ws[4][3];
    int lane = t & 31, wid = t >> 5;
    if (lane == 0) { ws[wid][0] = s0; ws[wid][1] = s1; ws[wid][2] = s2; }
    __syncthreads();
    float n0 = ws[0][0] + ws[1][0] + ws[2][0] + ws[3][0];
    float n1 = ws[0][1] + ws[1][1] + ws[2][1] + ws[3][1];
    float dp = ws[0][2] + ws[1][2] + ws[2][2] + ws[3][2];
    float invR = 1.0f / fmaxf(sqrtf(n0), 1e-8f);
    float invP = 1.0f / fmaxf(sqrtf(n1), 1e-8f);
    g_nrep_bf16[row * ZD + t] = __float2bfloat16(v * invR);
    if (t == 0) {
        g_pos[row] = dp * invR * invP;
        g_rowsum[row] = 0.0f;
        if (row == 0) { g_scalar = 0.0f; g_ticket = 0u; }
    }
}

// ---------------------------------------------------------------------------
// Kernel 2: fused sim GEMM (mma.sync bf16) + exp + diag mask + row sums +
// ticket-gated final scalar reduce. Upper-triangular tile set only (sim is
// symmetric): off-diagonal tiles also accumulate column sums into the
// transposed rows. CTA = 128x128 tile, 256 threads = 8 warps (4m x 2n).
// ---------------------------------------------------------------------------
__global__ void __launch_bounds__(256, 2) simgemm_kernel(float* __restrict__ out) {
    extern __shared__ __nv_bfloat16 smem[];
    __nv_bfloat16* sA = smem;
    __nv_bfloat16* sB = smem + BM * STRIDE;

    int tid = threadIdx.x;
    int wid = tid >> 5, lane = tid & 31;

    // Closed-form upper-triangle decode (ty <= tx), with fixup
    int idx = blockIdx.x;
    int ty = (int)(0.5f * (2.0f * ROW_TILES + 1.0f
              - sqrtf((2.0f * ROW_TILES + 1.0f) * (2.0f * ROW_TILES + 1.0f)
                      - 8.0f * (float)idx)));
    if (ty > 0 && ty * ROW_TILES - ty * (ty - 1) / 2 > idx) ty--;
    while ((ty + 1) * ROW_TILES - (ty + 1) * ty / 2 <= idx) ty++;
    int tx = ty + (idx - (ty * ROW_TILES - ty * (ty - 1) / 2));

    int rowBase = ty * BM;
    int colBase = tx * BN;
    bool diag = (tx == ty);

    // ---- Load A/B tiles [128 x 128] bf16 via cp.async (16B chunks)
    #pragma unroll
    for (int it = 0; it < 8; it++) {
        int i2 = it * 256 + tid;          // 2048 16B-chunks per tile
        int r = i2 >> 4, c = i2 & 15;
        uint32_t da = (uint32_t)__cvta_generic_to_shared(sA + r * STRIDE + c * 8);
        const void* ga = g_nrep_bf16 + (size_t)(rowBase + r) * ZD + c * 8;
        asm volatile("cp.async.cg.shared.global [%0], [%1], 16;" :: "r"(da), "l"(ga));
        uint32_t db = (uint32_t)__cvta_generic_to_shared(sB + r * STRIDE + c * 8);
        const void* gb = g_nrep_bf16 + (size_t)(colBase + r) * ZD + c * 8;
        asm volatile("cp.async.cg.shared.global [%0], [%1], 16;" :: "r"(db), "l"(gb));
    }
    asm volatile("cp.async.commit_group;" ::: "memory");
    asm volatile("cp.async.wait_group 0;" ::: "memory");
    __syncthreads();

    int wm = wid & 3;        // warp row (4)
    int wn = wid >> 2;       // warp col (2)

    float acc[2][8][4];
    #pragma unroll
    for (int mt = 0; mt < 2; mt++)
        #pragma unroll
        for (int nt = 0; nt < 8; nt++)
            #pragma unroll
            for (int e = 0; e < 4; e++) acc[mt][nt][e] = 0.0f;

    // ldmatrix base addresses (per lane); k advances by 32B per k-step
    uint32_t aAddr[2];
    #pragma unroll
    for (int mt = 0; mt < 2; mt++) {
        int row = wm * 32 + mt * 16 + (lane & 15);
        int k = (lane >> 4) * 8;
        aAddr[mt] = (uint32_t)__cvta_generic_to_shared(sA + row * STRIDE + k);
    }
    uint32_t bAddr[4];
    #pragma unroll
    for (int ntp = 0; ntp < 4; ntp++) {
        int n = wn * 64 + ntp * 16 + ((lane >> 4) & 1) * 8 + (lane & 7);
        int k = ((lane >> 3) & 1) * 8;
        bAddr[ntp] = (uint32_t)__cvta_generic_to_shared(sB + n * STRIDE + k);
    }

    // ---- Mainloop: 8 k-steps of k16
    #pragma unroll
    for (int ks = 0; ks < 8; ks++) {
        uint32_t a[2][4];
        #pragma unroll
        for (int mt = 0; mt < 2; mt++)
            asm volatile("ldmatrix.sync.aligned.m8n8.x4.shared.b16 {%0,%1,%2,%3}, [%4];"
                : "=r"(a[mt][0]), "=r"(a[mt][1]), "=r"(a[mt][2]), "=r"(a[mt][3])
                : "r"(aAddr[mt] + ks * 32));
        uint32_t b[8][2];
        #pragma unroll
        for (int ntp = 0; ntp < 4; ntp++)
            asm volatile("ldmatrix.sync.aligned.m8n8.x4.shared.b16 {%0,%1,%2,%3}, [%4];"
                : "=r"(b[2*ntp][0]), "=r"(b[2*ntp][1]),
                  "=r"(b[2*ntp+1][0]), "=r"(b[2*ntp+1][1])
                : "r"(bAddr[ntp] + ks * 32));
        #pragma unroll
        for (int mt = 0; mt < 2; mt++)
            #pragma unroll
            for (int nt = 0; nt < 8; nt++)
                asm volatile(
                    "mma.sync.aligned.m16n8k16.row.col.f32.bf16.bf16.f32 "
                    "{%0,%1,%2,%3}, {%4,%5,%6,%7}, {%8,%9}, {%0,%1,%2,%3};"
                    : "+f"(acc[mt][nt][0]), "+f"(acc[mt][nt][1]),
                      "+f"(acc[mt][nt][2]), "+f"(acc[mt][nt][3])
                    : "r"(a[mt][0]), "r"(a[mt][1]), "r"(a[mt][2]), "r"(a[mt][3]),
                      "r"(b[nt][0]), "r"(b[nt][1]));
    }

    // ---- Epilogue: e = exp(sim/T), self-diag masked.
    int g = lane >> 2, t = lane & 3;

    float colacc[16];
    #pragma unroll
    for (int c = 0; c < 16; c++) colacc[c] = 0.0f;

    #pragma unroll
    for (int mt = 0; mt < 2; mt++) {
        #pragma unroll
        for (int half = 0; half < 2; half++) {
            int i = rowBase + wm * 32 + mt * 16 + half * 8 + g;
            int jbase = colBase + wn * 64 + t * 2;
            float s = 0.0f;
            #pragma unroll
            for (int nt = 0; nt < 8; nt++) {
                #pragma unroll
                for (int e = 0; e < 2; e++) {
                    float v = acc[mt][nt][half * 2 + e];
                    float ex;
                    asm("ex2.approx.f32 %0, %1;" : "=f"(ex) : "f"(v * EXP_SCALE));
                    if (diag && (i == jbase + nt * 8 + e)) ex = 0.0f;
                    s += ex;
                    colacc[nt * 2 + e] += ex;
                }
            }
            s += __shfl_xor_sync(0xFFFFFFFFu, s, 1);
            s += __shfl_xor_sync(0xFFFFFFFFu, s, 2);
            if (t == 0) atomicAdd(&g_rowsum[i], s);
        }
    }

    if (!diag) {
        #pragma unroll
        for (int c = 0; c < 16; c++) {
            float v = colacc[c];
            v += __shfl_xor_sync(0xFFFFFFFFu, v, 4);
            v += __shfl_xor_sync(0xFFFFFFFFu, v, 8);
            v += __shfl_xor_sync(0xFFFFFFFFu, v, 16);
            colacc[c] = v;
        }
        if (g == 0) {
            int jbase = colBase + wn * 64 + t * 2;
            #pragma unroll
            for (int c = 0; c < 16; c++) {
                int j = jbase + (c >> 1) * 8 + (c & 1);
                atomicAdd(&g_rowsum[j], colacc[c]);
            }
        }
    }

    // ---- Ticket: last CTA computes the scalar loss
    __shared__ bool is_last;
    __syncthreads();
    if (tid == 0) {
        __threadfence();
        unsigned int tk = atomicInc(&g_ticket, 0xFFFFFFFFu);
        is_last = (tk == (unsigned int)(gridDim.x - 1));
    }
    __syncthreads();
    if (is_last) {
        __threadfence();
        float acc2 = 0.0f;
        for (int i = tid; i < TWO_N; i += 256)
            acc2 += logf(__ldcg(&g_rowsum[i])) - g_pos[i] * INV_T;
        #pragma unroll
        for (int o = 16; o > 0; o >>= 1)
            acc2 += __shfl_xor_sync(0xFFFFFFFFu, acc2, o);
        __shared__ float sred[8];
        if ((tid & 31) == 0) sred[tid >> 5] = acc2;
        __syncthreads();
        if (tid == 0) {
            float tot = 0.0f;
            #pragma unroll
            for (int w = 0; w < 8; w++) tot += sred[w];
            out[0] = tot * (1.0f / (float)TWO_N);
        }
    }
}

// ---------------------------------------------------------------------------
extern "C" void kernel_launch(void* const* d_in, const int* in_sizes, int n_in,
                              void* d_out, int out_size) {
    const float* z1 = (const float*)d_in[0];
    const float* z2 = (const float*)d_in[1];

    cudaFuncSetAttribute(simgemm_kernel,
                         cudaFuncAttributeMaxDynamicSharedMemorySize, SMEM_SZ);

    normalize_pos_kernel<<<TWO_N, 128>>>(z1, z2);
    simgemm_kernel<<<NUM_TILES, 256, SMEM_SZ>>>((float*)d_out);
}

// round 5
// speedup vs baseline: 1.0736x; 1.0736x over previous
#include <cuda_runtime.h>
#include <cuda_bf16.h>
#include <cstdint>

// NT-Xent fused: N=4096, Z=128, T=0.5
#define TWO_N 8192
#define ZD 128
#define INV_T 2.0f
#define EXP_SCALE 2.8853900817779268f   // INV_T * log2(e)
#define LN2F 0.6931471805599453f

#define BM 128
#define BN 128
#define ROW_TILES (TWO_N / BM)           // 64
#define NUM_CTAS 1056                    // sum_ty ceil((64-ty)/2)
#define STRIDE 136                       // bf16 elems per smem row (128 + 8 pad)
#define TILE_BYTES (BM * STRIDE * 2)     // 34816
#define SMEM_SZ (3 * TILE_BYTES)         // A + B0 + B1 = 104448

// Scratch (device globals — no allocation allowed)
__device__ __nv_bfloat16 g_nrep_bf16[TWO_N * ZD];
__device__ float         g_rowsum  [TWO_N];
__device__ float         g_pos     [TWO_N];
__device__ unsigned int  g_ticket;

// ---------------------------------------------------------------------------
// Kernel 1: normalize both rows of each positive pair (j, j+N) in one block;
// emit bf16 rows, fp32 positives, zero rowsums. 4096 blocks x 128 threads.
// ---------------------------------------------------------------------------
__global__ void normalize_pos_kernel(const float* __restrict__ z1,
                                     const float* __restrict__ z2) {
    int j = blockIdx.x;                      // 0..4095
    int t = threadIdx.x;
    float v = z1[(size_t)j * ZD + t];
    float p = z2[(size_t)j * ZD + t];
    float s0 = v * v, s1 = p * p, s2 = v * p;
    #pragma unroll
    for (int o = 16; o > 0; o >>= 1) {
        s0 += __shfl_xor_sync(0xFFFFFFFFu, s0, o);
        s1 += __shfl_xor_sync(0xFFFFFFFFu, s1, o);
        s2 += __shfl_xor_sync(0xFFFFFFFFu, s2, o);
    }
    __shared__ float ws[4][3];
    int lane = t & 31, wid = t >> 5;
    if (lane == 0) { ws[wid][0] = s0; ws[wid][1] = s1; ws[wid][2] = s2; }
    __syncthreads();
    float n0 = ws[0][0] + ws[1][0] + ws[2][0] + ws[3][0];
    float n1 = ws[0][1] + ws[1][1] + ws[2][1] + ws[3][1];
    float dp = ws[0][2] + ws[1][2] + ws[2][2] + ws[3][2];
    float invA = 1.0f / fmaxf(sqrtf(n0), 1e-8f);
    float invB = 1.0f / fmaxf(sqrtf(n1), 1e-8f);
    g_nrep_bf16[(size_t)j * ZD + t]             = __float2bfloat16(v * invA);
    g_nrep_bf16[(size_t)(j + TWO_N/2) * ZD + t] = __float2bfloat16(p * invB);
    if (t == 0) {
        float pos = dp * invA * invB;
        g_pos[j] = pos;
        g_pos[j + TWO_N/2] = pos;
        g_rowsum[j] = 0.0f;
        g_rowsum[j + TWO_N/2] = 0.0f;
        if (j == 0) g_ticket = 0u;
    }
}

// ---------------------------------------------------------------------------
// Epilogue helper: exp, optional diag mask, row sums + column sums (symmetry)
// ---------------------------------------------------------------------------
__device__ __forceinline__ void epilogue(float (&acc)[2][8][4], int rowBase,
                                         int colBase, int wm, int wn,
                                         int lane, bool diag) {
    int g = lane >> 2, t = lane & 3;
    float colacc[16];
    #pragma unroll
    for (int c = 0; c < 16; c++) colacc[c] = 0.0f;

    #pragma unroll
    for (int mt = 0; mt < 2; mt++) {
        #pragma unroll
        for (int half = 0; half < 2; half++) {
            int i = rowBase + wm * 32 + mt * 16 + half * 8 + g;
            int jbase = colBase + wn * 64 + t * 2;
            float s = 0.0f;
            #pragma unroll
            for (int nt = 0; nt < 8; nt++) {
                #pragma unroll
                for (int e = 0; e < 2; e++) {
                    float v = acc[mt][nt][half * 2 + e];
                    float ex;
                    asm("ex2.approx.f32 %0, %1;" : "=f"(ex) : "f"(v * EXP_SCALE));
                    if (diag && (i == jbase + nt * 8 + e)) ex = 0.0f;
                    s += ex;
                    colacc[nt * 2 + e] += ex;
                }
            }
            s += __shfl_xor_sync(0xFFFFFFFFu, s, 1);
            s += __shfl_xor_sync(0xFFFFFFFFu, s, 2);
            if (t == 0) atomicAdd(&g_rowsum[i], s);
        }
    }

    if (!diag) {
        #pragma unroll
        for (int c = 0; c < 16; c++) {
            float v = colacc[c];
            v += __shfl_xor_sync(0xFFFFFFFFu, v, 4);
            v += __shfl_xor_sync(0xFFFFFFFFu, v, 8);
            v += __shfl_xor_sync(0xFFFFFFFFu, v, 16);
            colacc[c] = v;
        }
        if (g == 0) {
            int jbase = colBase + wn * 64 + t * 2;
            #pragma unroll
            for (int c = 0; c < 16; c++) {
                int j = jbase + (c >> 1) * 8 + (c & 1);
                atomicAdd(&g_rowsum[j], colacc[c]);
            }
        }
    }
}

// ---------------------------------------------------------------------------
// Kernel 2: fused sim GEMM. Each CTA = one 128-row strip x TWO 128-col tiles
// sharing the A tile (upper triangle of symmetric sim => also column sums).
// B1 prefetched via a second cp.async group; its latency hides under tile0.
// Last CTA (ticket) computes the scalar loss with fast log2.
// ---------------------------------------------------------------------------
__global__ void __launch_bounds__(256, 2) simgemm_kernel(float* __restrict__ out) {
    extern __shared__ __nv_bfloat16 smem[];
    __nv_bfloat16* sA = smem;
    __nv_bfloat16* sB = smem + BM * STRIDE;     // B0; B1 at +TILE_BYTES

    int tid = threadIdx.x;
    int wid = tid >> 5, lane = tid & 31;

    // Decode pair index -> (ty, tx0): row ty has ceil((64-ty)/2) pairs
    int p = blockIdx.x, ty = 0;
    int rowPairs = 32;
    while (p >= rowPairs) { p -= rowPairs; ty++; rowPairs = (65 - ty) >> 1; }
    int tx0 = ty + 2 * p;
    bool hasT1 = (tx0 + 1) < ROW_TILES;
    int tx1 = hasT1 ? (tx0 + 1) : tx0;          // clamp (discarded if !hasT1)

    int rowBase = ty * BM;

    // ---- cp.async loads: group0 = A + B0, group1 = B1
    #pragma unroll
    for (int it = 0; it < 8; it++) {
        int i2 = it * 256 + tid;          // 2048 16B-chunks per tile
        int r = i2 >> 4, c = i2 & 15;
        uint32_t da = (uint32_t)__cvta_generic_to_shared(sA + r * STRIDE + c * 8);
        const void* ga = g_nrep_bf16 + (size_t)(rowBase + r) * ZD + c * 8;
        asm volatile("cp.async.cg.shared.global [%0], [%1], 16;" :: "r"(da), "l"(ga));
        uint32_t db = (uint32_t)__cvta_generic_to_shared(sB + r * STRIDE + c * 8);
        const void* gb = g_nrep_bf16 + (size_t)(tx0 * BN + r) * ZD + c * 8;
        asm volatile("cp.async.cg.shared.global [%0], [%1], 16;" :: "r"(db), "l"(gb));
    }
    asm volatile("cp.async.commit_group;" ::: "memory");
    #pragma unroll
    for (int it = 0; it < 8; it++) {
        int i2 = it * 256 + tid;
        int r = i2 >> 4, c = i2 & 15;
        uint32_t db = (uint32_t)__cvta_generic_to_shared(
            (char*)sB + TILE_BYTES + (r * STRIDE + c * 8) * 2);
        const void* gb = g_nrep_bf16 + (size_t)(tx1 * BN + r) * ZD + c * 8;
        asm volatile("cp.async.cg.shared.global [%0], [%1], 16;" :: "r"(db), "l"(gb));
    }
    asm volatile("cp.async.commit_group;" ::: "memory");

    int wm = wid & 3;        // warp row (4)
    int wn = wid >> 2;       // warp col (2)

    // ldmatrix base addresses (per lane); k advances by 32B per k-step
    uint32_t aAddr[2];
    #pragma unroll
    for (int mt = 0; mt < 2; mt++) {
        int row = wm * 32 + mt * 16 + (lane & 15);
        int k = (lane >> 4) * 8;
        aAddr[mt] = (uint32_t)__cvta_generic_to_shared(sA + row * STRIDE + k);
    }
    uint32_t bAddr[4];
    #pragma unroll
    for (int ntp = 0; ntp < 4; ntp++) {
        int n = wn * 64 + ntp * 16 + ((lane >> 4) & 1) * 8 + (lane & 7);
        int k = ((lane >> 3) & 1) * 8;
        bAddr[ntp] = (uint32_t)__cvta_generic_to_shared(sB + n * STRIDE + k);
    }

    int ntiles = hasT1 ? 2 : 1;
    #pragma unroll 1
    for (int tile = 0; tile < ntiles; tile++) {
        if (tile == 0) { asm volatile("cp.async.wait_group 1;" ::: "memory"); }
        else           { asm volatile("cp.async.wait_group 0;" ::: "memory"); }
        __syncthreads();

        float acc[2][8][4];
        #pragma unroll
        for (int mt = 0; mt < 2; mt++)
            #pragma unroll
            for (int nt = 0; nt < 8; nt++)
                #pragma unroll
                for (int e = 0; e < 4; e++) acc[mt][nt][e] = 0.0f;

        uint32_t bOff = tile * TILE_BYTES;

        // ---- Mainloop: 8 k-steps of k16
        #pragma unroll
        for (int ks = 0; ks < 8; ks++) {
            uint32_t a[2][4];
            #pragma unroll
            for (int mt = 0; mt < 2; mt++)
                asm volatile("ldmatrix.sync.aligned.m8n8.x4.shared.b16 {%0,%1,%2,%3}, [%4];"
                    : "=r"(a[mt][0]), "=r"(a[mt][1]), "=r"(a[mt][2]), "=r"(a[mt][3])
                    : "r"(aAddr[mt] + ks * 32));
            uint32_t b[8][2];
            #pragma unroll
            for (int ntp = 0; ntp < 4; ntp++)
                asm volatile("ldmatrix.sync.aligned.m8n8.x4.shared.b16 {%0,%1,%2,%3}, [%4];"
                    : "=r"(b[2*ntp][0]), "=r"(b[2*ntp][1]),
                      "=r"(b[2*ntp+1][0]), "=r"(b[2*ntp+1][1])
                    : "r"(bAddr[ntp] + bOff + ks * 32));
            #pragma unroll
            for (int mt = 0; mt < 2; mt++)
                #pragma unroll
                for (int nt = 0; nt < 8; nt++)
                    asm volatile(
                        "mma.sync.aligned.m16n8k16.row.col.f32.bf16.bf16.f32 "
                        "{%0,%1,%2,%3}, {%4,%5,%6,%7}, {%8,%9}, {%0,%1,%2,%3};"
                        : "+f"(acc[mt][nt][0]), "+f"(acc[mt][nt][1]),
                          "+f"(acc[mt][nt][2]), "+f"(acc[mt][nt][3])
                        : "r"(a[mt][0]), "r"(a[mt][1]), "r"(a[mt][2]), "r"(a[mt][3]),
                          "r"(b[nt][0]), "r"(b[nt][1]));
        }

        bool diag = (tile == 0) && (tx0 == ty);  // tile1 is always off-diagonal
        epilogue(acc, rowBase, (tx0 + tile) * BN, wm, wn, lane, diag);
    }

    // ---- Ticket: last CTA computes the scalar loss (fast log2)
    __shared__ bool is_last;
    __syncthreads();
    if (tid == 0) {
        __threadfence();
        unsigned int tk = atomicInc(&g_ticket, 0xFFFFFFFFu);
        is_last = (tk == (unsigned int)(gridDim.x - 1));
    }
    __syncthreads();
    if (is_last) {
        __threadfence();
        float acc2 = 0.0f;
        #pragma unroll 4
        for (int i = tid; i < TWO_N; i += 256)
            acc2 += __log2f(__ldcg(&g_rowsum[i])) * LN2F - g_pos[i] * INV_T;
        #pragma unroll
        for (int o = 16; o > 0; o >>= 1)
            acc2 += __shfl_xor_sync(0xFFFFFFFFu, acc2, o);
        __shared__ float sred[8];
        if ((tid & 31) == 0) sred[tid >> 5] = acc2;
        __syncthreads();
        if (tid == 0) {
            float tot = 0.0f;
            #pragma unroll
            for (int w = 0; w < 8; w++) tot += sred[w];
            out[0] = tot * (1.0f / (float)TWO_N);
        }
    }
}

// ---------------------------------------------------------------------------
extern "C" void kernel_launch(void* const* d_in, const int* in_sizes, int n_in,
                              void* d_out, int out_size) {
    const float* z1 = (const float*)d_in[0];
    const float* z2 = (const float*)d_in[1];

    cudaFuncSetAttribute(simgemm_kernel,
                         cudaFuncAttributeMaxDynamicSharedMemorySize, SMEM_SZ);

    normalize_pos_kernel<<<TWO_N / 2, 128>>>(z1, z2);
    simgemm_kernel<<<NUM_CTAS, 256, SMEM_SZ>>>((float*)d_out);
}

// round 6
// speedup vs baseline: 1.0768x; 1.0030x over previous
#include <cuda_runtime.h>
#include <cuda_bf16.h>
#include <cstdint>

// NT-Xent fused: N=4096, Z=128, T=0.5
#define TWO_N 8192
#define ZD 128
#define INV_T 2.0f
#define EXP_SCALE 2.8853900817779268f   // INV_T * log2(e)
#define LN2F 0.6931471805599453f

#define BM 128
#define BN 128
#define ROW_TILES (TWO_N / BM)                       // 64
#define NUM_TILES (ROW_TILES * (ROW_TILES + 1) / 2)  // 2080 (upper triangle)
#define STRIDE 136                       // bf16 elems per smem row (128 + 8 pad)
#define SMEM_SZ (2 * BM * STRIDE * 2)    // 69632

// Scratch (device globals — no allocation allowed)
__device__ __nv_bfloat16 g_nrep_bf16[TWO_N * ZD];
__device__ float         g_rowsum  [TWO_N];
__device__ float         g_pos     [TWO_N];
__device__ unsigned int  g_ticket;

// ---------------------------------------------------------------------------
// Kernel 1: normalize both rows of each positive pair (j, j+N) in one block;
// emit bf16 rows, fp32 positives, zero rowsums. 4096 blocks x 128 threads.
// ---------------------------------------------------------------------------
__global__ void normalize_pos_kernel(const float* __restrict__ z1,
                                     const float* __restrict__ z2) {
    int j = blockIdx.x;                      // 0..4095
    int t = threadIdx.x;
    float v = z1[(size_t)j * ZD + t];
    float p = z2[(size_t)j * ZD + t];
    float s0 = v * v, s1 = p * p, s2 = v * p;
    #pragma unroll
    for (int o = 16; o > 0; o >>= 1) {
        s0 += __shfl_xor_sync(0xFFFFFFFFu, s0, o);
        s1 += __shfl_xor_sync(0xFFFFFFFFu, s1, o);
        s2 += __shfl_xor_sync(0xFFFFFFFFu, s2, o);
    }
    __shared__ float ws[4][3];
    int lane = t & 31, wid = t >> 5;
    if (lane == 0) { ws[wid][0] = s0; ws[wid][1] = s1; ws[wid][2] = s2; }
    __syncthreads();
    float n0 = ws[0][0] + ws[1][0] + ws[2][0] + ws[3][0];
    float n1 = ws[0][1] + ws[1][1] + ws[2][1] + ws[3][1];
    float dp = ws[0][2] + ws[1][2] + ws[2][2] + ws[3][2];
    float invA = 1.0f / fmaxf(sqrtf(n0), 1e-8f);
    float invB = 1.0f / fmaxf(sqrtf(n1), 1e-8f);
    g_nrep_bf16[(size_t)j * ZD + t]             = __float2bfloat16(v * invA);
    g_nrep_bf16[(size_t)(j + TWO_N/2) * ZD + t] = __float2bfloat16(p * invB);
    if (t == 0) {
        float pos = dp * invA * invB;
        g_pos[j] = pos;
        g_pos[j + TWO_N/2] = pos;
        g_rowsum[j] = 0.0f;
        g_rowsum[j + TWO_N/2] = 0.0f;
        if (j == 0) g_ticket = 0u;
    }
}

// ---------------------------------------------------------------------------
// Kernel 2: fused sim GEMM (mma.sync bf16) + exp + diag mask + row/col sums.
// Upper-triangular tiles only (sim symmetric). CTA = 128x128 tile,
// 512 threads = 16 warps (4m x 4n), warp tile 32x32 -> 32 acc regs/thread.
// launch_bounds(512,2): 64-reg cap -> 32 warps/SM resident.
// ---------------------------------------------------------------------------
__global__ void __launch_bounds__(512, 2) simgemm_kernel(float* __restrict__ out) {
    extern __shared__ __nv_bfloat16 smem[];
    __nv_bfloat16* sA = smem;
    __nv_bfloat16* sB = smem + BM * STRIDE;

    int tid = threadIdx.x;
    int wid = tid >> 5, lane = tid & 31;

    // Decode linear tile index -> upper-triangle (ty <= tx)
    int rem = blockIdx.x, ty = 0;
    while (rem >= ROW_TILES - ty) { rem -= ROW_TILES - ty; ty++; }
    int tx = ty + rem;

    int rowBase = ty * BM;
    int colBase = tx * BN;
    bool diag = (tx == ty);

    // ---- Load A/B tiles [128 x 128] bf16 via cp.async (16B chunks)
    #pragma unroll
    for (int it = 0; it < 4; it++) {
        int i2 = it * 512 + tid;          // 2048 16B-chunks per tile
        int r = i2 >> 4, c = i2 & 15;
        uint32_t da = (uint32_t)__cvta_generic_to_shared(sA + r * STRIDE + c * 8);
        const void* ga = g_nrep_bf16 + (size_t)(rowBase + r) * ZD + c * 8;
        asm volatile("cp.async.cg.shared.global [%0], [%1], 16;" :: "r"(da), "l"(ga));
        uint32_t db = (uint32_t)__cvta_generic_to_shared(sB + r * STRIDE + c * 8);
        const void* gb = g_nrep_bf16 + (size_t)(colBase + r) * ZD + c * 8;
        asm volatile("cp.async.cg.shared.global [%0], [%1], 16;" :: "r"(db), "l"(gb));
    }
    asm volatile("cp.async.commit_group;" ::: "memory");
    asm volatile("cp.async.wait_group 0;" ::: "memory");
    __syncthreads();

    int wm = wid & 3;        // warp row (4)
    int wn = wid >> 2;       // warp col (4)

    float acc[2][4][4];
    #pragma unroll
    for (int mt = 0; mt < 2; mt++)
        #pragma unroll
        for (int nt = 0; nt < 4; nt++)
            #pragma unroll
            for (int e = 0; e < 4; e++) acc[mt][nt][e] = 0.0f;

    // ldmatrix base addresses (per lane); k advances by 32B per k-step
    uint32_t aAddr[2];
    #pragma unroll
    for (int mt = 0; mt < 2; mt++) {
        int row = wm * 32 + mt * 16 + (lane & 15);
        int k = (lane >> 4) * 8;
        aAddr[mt] = (uint32_t)__cvta_generic_to_shared(sA + row * STRIDE + k);
    }
    uint32_t bAddr[2];
    #pragma unroll
    for (int ntp = 0; ntp < 2; ntp++) {
        int n = wn * 32 + ntp * 16 + ((lane >> 4) & 1) * 8 + (lane & 7);
        int k = ((lane >> 3) & 1) * 8;
        bAddr[ntp] = (uint32_t)__cvta_generic_to_shared(sB + n * STRIDE + k);
    }

    // ---- Mainloop: 8 k-steps of k16
    #pragma unroll
    for (int ks = 0; ks < 8; ks++) {
        uint32_t a[2][4];
        #pragma unroll
        for (int mt = 0; mt < 2; mt++)
            asm volatile("ldmatrix.sync.aligned.m8n8.x4.shared.b16 {%0,%1,%2,%3}, [%4];"
                : "=r"(a[mt][0]), "=r"(a[mt][1]), "=r"(a[mt][2]), "=r"(a[mt][3])
                : "r"(aAddr[mt] + ks * 32));
        uint32_t b[4][2];
        #pragma unroll
        for (int ntp = 0; ntp < 2; ntp++)
            asm volatile("ldmatrix.sync.aligned.m8n8.x4.shared.b16 {%0,%1,%2,%3}, [%4];"
                : "=r"(b[2*ntp][0]), "=r"(b[2*ntp][1]),
                  "=r"(b[2*ntp+1][0]), "=r"(b[2*ntp+1][1])
                : "r"(bAddr[ntp] + ks * 32));
        #pragma unroll
        for (int mt = 0; mt < 2; mt++)
            #pragma unroll
            for (int nt = 0; nt < 4; nt++)
                asm volatile(
                    "mma.sync.aligned.m16n8k16.row.col.f32.bf16.bf16.f32 "
                    "{%0,%1,%2,%3}, {%4,%5,%6,%7}, {%8,%9}, {%0,%1,%2,%3};"
                    : "+f"(acc[mt][nt][0]), "+f"(acc[mt][nt][1]),
                      "+f"(acc[mt][nt][2]), "+f"(acc[mt][nt][3])
                    : "r"(a[mt][0]), "r"(a[mt][1]), "r"(a[mt][2]), "r"(a[mt][3]),
                      "r"(b[nt][0]), "r"(b[nt][1]));
    }

    // ---- Epilogue: e = exp(sim/T), self-diag masked; row sums + col sums
    int g = lane >> 2, t = lane & 3;

    float colacc[8];
    #pragma unroll
    for (int c = 0; c < 8; c++) colacc[c] = 0.0f;

    #pragma unroll
    for (int mt = 0; mt < 2; mt++) {
        #pragma unroll
        for (int half = 0; half < 2; half++) {
            int i = rowBase + wm * 32 + mt * 16 + half * 8 + g;
            int jbase = colBase + wn * 32 + t * 2;
            float s = 0.0f;
            #pragma unroll
            for (int nt = 0; nt < 4; nt++) {
                #pragma unroll
                for (int e = 0; e < 2; e++) {
                    float v = acc[mt][nt][half * 2 + e];
                    float ex;
                    asm("ex2.approx.f32 %0, %1;" : "=f"(ex) : "f"(v * EXP_SCALE));
                    if (diag && (i == jbase + nt * 8 + e)) ex = 0.0f;
                    s += ex;
                    colacc[nt * 2 + e] += ex;
                }
            }
            s += __shfl_xor_sync(0xFFFFFFFFu, s, 1);
            s += __shfl_xor_sync(0xFFFFFFFFu, s, 2);
            if (t == 0) atomicAdd(&g_rowsum[i], s);
        }
    }

    if (!diag) {
        // Sum column partials over the 8 row-groups (xor 4,8,16 keep t fixed)
        #pragma unroll
        for (int c = 0; c < 8; c++) {
            float v = colacc[c];
            v += __shfl_xor_sync(0xFFFFFFFFu, v, 4);
            v += __shfl_xor_sync(0xFFFFFFFFu, v, 8);
            v += __shfl_xor_sync(0xFFFFFFFFu, v, 16);
            colacc[c] = v;
        }
        if (g == 0) {
            int jbase = colBase + wn * 32 + t * 2;
            #pragma unroll
            for (int c = 0; c < 8; c++) {
                int j = jbase + (c >> 1) * 8 + (c & 1);
                atomicAdd(&g_rowsum[j], colacc[c]);
            }
        }
    }

    // ---- Ticket: last CTA computes the scalar loss (fast log2)
    __shared__ bool is_last;
    __syncthreads();
    if (tid == 0) {
        __threadfence();
        unsigned int tk = atomicInc(&g_ticket, 0xFFFFFFFFu);
        is_last = (tk == (unsigned int)(gridDim.x - 1));
    }
    __syncthreads();
    if (is_last) {
        __threadfence();
        float acc2 = 0.0f;
        #pragma unroll 4
        for (int i = tid; i < TWO_N; i += 512)
            acc2 += __log2f(__ldcg(&g_rowsum[i])) * LN2F - g_pos[i] * INV_T;
        #pragma unroll
        for (int o = 16; o > 0; o >>= 1)
            acc2 += __shfl_xor_sync(0xFFFFFFFFu, acc2, o);
        __shared__ float sred[16];
        if ((tid & 31) == 0) sred[tid >> 5] = acc2;
        __syncthreads();
        if (tid == 0) {
            float tot = 0.0f;
            #pragma unroll
            for (int w = 0; w < 16; w++) tot += sred[w];
            out[0] = tot * (1.0f / (float)TWO_N);
        }
    }
}

// ---------------------------------------------------------------------------
extern "C" void kernel_launch(void* const* d_in, const int* in_sizes, int n_in,
                              void* d_out, int out_size) {
    const float* z1 = (const float*)d_in[0];
    const float* z2 = (const float*)d_in[1];

    cudaFuncSetAttribute(simgemm_kernel,
                         cudaFuncAttributeMaxDynamicSharedMemorySize, SMEM_SZ);

    normalize_pos_kernel<<<TWO_N / 2, 128>>>(z1, z2);
    simgemm_kernel<<<NUM_TILES, 512, SMEM_SZ>>>((float*)d_out);
}

// round 7
// speedup vs baseline: 1.1649x; 1.0818x over previous
#include <cuda_runtime.h>
#include <cuda_bf16.h>
#include <cstdint>

// NT-Xent fused: N=4096, Z=128, T=0.5
#define TWO_N 8192
#define ZD 128
#define INV_T 2.0f
// exp(sim/T) = 2^(sim * INV_T * log2(e)) ; fold sqrt of that scale into each
// stored bf16 row so the MMA accumulator is directly the ex2 argument.
#define SQRT_EXP_SCALE 1.6986435651438231f   // sqrt(INV_T * log2(e))
#define LN2F 0.6931471805599453f

#define BM 128
#define BN 128
#define ROW_TILES (TWO_N / BM)                       // 64
#define NUM_TILES (ROW_TILES * (ROW_TILES + 1) / 2)  // 2080 (upper triangle)
#define STRIDE 136                       // bf16 elems per smem row (128 + 8 pad)
#define SMEM_SZ (2 * BM * STRIDE * 2)    // 69632

// Scratch (device globals — no allocation allowed)
__device__ __nv_bfloat16 g_nrep_bf16[TWO_N * ZD];
__device__ float         g_rowsum  [TWO_N];
__device__ float         g_pos     [TWO_N];
__device__ unsigned int  g_ticket;

// ---------------------------------------------------------------------------
// Kernel 1: normalize both rows of each positive pair (j, j+N) in one block;
// emit pre-scaled bf16 rows, fp32 positives, zero rowsums. 4096 blocks x 128.
// ---------------------------------------------------------------------------
__global__ void normalize_pos_kernel(const float* __restrict__ z1,
                                     const float* __restrict__ z2) {
    int j = blockIdx.x;                      // 0..4095
    int t = threadIdx.x;
    float v = z1[(size_t)j * ZD + t];
    float p = z2[(size_t)j * ZD + t];
    float s0 = v * v, s1 = p * p, s2 = v * p;
    #pragma unroll
    for (int o = 16; o > 0; o >>= 1) {
        s0 += __shfl_xor_sync(0xFFFFFFFFu, s0, o);
        s1 += __shfl_xor_sync(0xFFFFFFFFu, s1, o);
        s2 += __shfl_xor_sync(0xFFFFFFFFu, s2, o);
    }
    __shared__ float ws[4][3];
    int lane = t & 31, wid = t >> 5;
    if (lane == 0) { ws[wid][0] = s0; ws[wid][1] = s1; ws[wid][2] = s2; }
    __syncthreads();
    float n0 = ws[0][0] + ws[1][0] + ws[2][0] + ws[3][0];
    float n1 = ws[0][1] + ws[1][1] + ws[2][1] + ws[3][1];
    float dp = ws[0][2] + ws[1][2] + ws[2][2] + ws[3][2];
    float invA = 1.0f / fmaxf(sqrtf(n0), 1e-8f);
    float invB = 1.0f / fmaxf(sqrtf(n1), 1e-8f);
    g_nrep_bf16[(size_t)j * ZD + t] =
        __float2bfloat16(v * (invA * SQRT_EXP_SCALE));
    g_nrep_bf16[(size_t)(j + TWO_N/2) * ZD + t] =
        __float2bfloat16(p * (invB * SQRT_EXP_SCALE));
    if (t == 0) {
        float pos = dp * invA * invB;
        g_pos[j] = pos;
        g_pos[j + TWO_N/2] = pos;
        g_rowsum[j] = 0.0f;
        g_rowsum[j + TWO_N/2] = 0.0f;
        if (j == 0) g_ticket = 0u;
    }
}

// ---------------------------------------------------------------------------
// Epilogue (templated on DIAG): ex = ex2(acc) (scale pre-folded), optional
// self-diag mask; row sums always, column sums (symmetry) for off-diag tiles.
// ---------------------------------------------------------------------------
template<bool DIAG>
__device__ __forceinline__ void epilogue(float (&acc)[2][4][4], int rowBase,
                                         int colBase, int wm, int wn, int lane) {
    int g = lane >> 2, t = lane & 3;

    float colacc[8];
    #pragma unroll
    for (int c = 0; c < 8; c++) colacc[c] = 0.0f;

    #pragma unroll
    for (int mt = 0; mt < 2; mt++) {
        #pragma unroll
        for (int half = 0; half < 2; half++) {
            int i = rowBase + wm * 32 + mt * 16 + half * 8 + g;
            float s = 0.0f;
            #pragma unroll
            for (int nt = 0; nt < 4; nt++) {
                #pragma unroll
                for (int e = 0; e < 2; e++) {
                    float ex;
                    asm("ex2.approx.f32 %0, %1;" : "=f"(ex)
                        : "f"(acc[mt][nt][half * 2 + e]));
                    if (DIAG) {
                        int j = colBase + wn * 32 + t * 2 + nt * 8 + e;
                        if (i == j) ex = 0.0f;
                    }
                    s += ex;
                    colacc[nt * 2 + e] += ex;
                }
            }
            s += __shfl_xor_sync(0xFFFFFFFFu, s, 1);
            s += __shfl_xor_sync(0xFFFFFFFFu, s, 2);
            if (t == 0) atomicAdd(&g_rowsum[i], s);
        }
    }

    if (!DIAG) {
        // Sum column partials over the 8 row-groups (xor 4,8,16 keep t fixed)
        #pragma unroll
        for (int c = 0; c < 8; c++) {
            float v = colacc[c];
            v += __shfl_xor_sync(0xFFFFFFFFu, v, 4);
            v += __shfl_xor_sync(0xFFFFFFFFu, v, 8);
            v += __shfl_xor_sync(0xFFFFFFFFu, v, 16);
            colacc[c] = v;
        }
        if (g == 0) {
            int jbase = colBase + wn * 32 + t * 2;
            #pragma unroll
            for (int c = 0; c < 8; c++) {
                int j = jbase + (c >> 1) * 8 + (c & 1);
                atomicAdd(&g_rowsum[j], colacc[c]);
            }
        }
    }
}

// ---------------------------------------------------------------------------
// Kernel 2: fused sim GEMM (mma.sync bf16) + exp + diag mask + row/col sums.
// Upper-triangular tiles only (sim symmetric). CTA = 128x128 tile,
// 512 threads = 16 warps (4m x 4n), warp tile 32x32.
// ---------------------------------------------------------------------------
__global__ void __launch_bounds__(512, 2) simgemm_kernel(float* __restrict__ out) {
    extern __shared__ __nv_bfloat16 smem[];
    __nv_bfloat16* sA = smem;
    __nv_bfloat16* sB = smem + BM * STRIDE;

    int tid = threadIdx.x;
    int wid = tid >> 5, lane = tid & 31;

    // Closed-form upper-triangle decode via reversed index:
    // r = 2079 - idx; m = largest with m(m+1)/2 <= r; ty = 63-m; tx = 63-(r-tri(m))
    int r = (NUM_TILES - 1) - (int)blockIdx.x;
    int m = (int)((sqrtf(8.0f * (float)r + 1.0f) - 1.0f) * 0.5f);
    while (m * (m + 1) / 2 > r) m--;
    while ((m + 1) * (m + 2) / 2 <= r) m++;
    int ty = (ROW_TILES - 1) - m;
    int tx = (ROW_TILES - 1) - (r - m * (m + 1) / 2);

    int rowBase = ty * BM;
    int colBase = tx * BN;
    bool diag = (tx == ty);

    // ---- Load A/B tiles [128 x 128] bf16 via cp.async (16B chunks)
    #pragma unroll
    for (int it = 0; it < 4; it++) {
        int i2 = it * 512 + tid;          // 2048 16B-chunks per tile
        int rr = i2 >> 4, c = i2 & 15;
        uint32_t da = (uint32_t)__cvta_generic_to_shared(sA + rr * STRIDE + c * 8);
        const void* ga = g_nrep_bf16 + (size_t)(rowBase + rr) * ZD + c * 8;
        asm volatile("cp.async.cg.shared.global [%0], [%1], 16;" :: "r"(da), "l"(ga));
        uint32_t db = (uint32_t)__cvta_generic_to_shared(sB + rr * STRIDE + c * 8);
        const void* gb = g_nrep_bf16 + (size_t)(colBase + rr) * ZD + c * 8;
        asm volatile("cp.async.cg.shared.global [%0], [%1], 16;" :: "r"(db), "l"(gb));
    }
    asm volatile("cp.async.commit_group;" ::: "memory");
    asm volatile("cp.async.wait_group 0;" ::: "memory");
    __syncthreads();

    int wm = wid & 3;        // warp row (4)
    int wn = wid >> 2;       // warp col (4)

    float acc[2][4][4];
    #pragma unroll
    for (int mt = 0; mt < 2; mt++)
        #pragma unroll
        for (int nt = 0; nt < 4; nt++)
            #pragma unroll
            for (int e = 0; e < 4; e++) acc[mt][nt][e] = 0.0f;

    // ldmatrix base addresses (per lane); k advances by 32B per k-step
    uint32_t aAddr[2];
    #pragma unroll
    for (int mt = 0; mt < 2; mt++) {
        int row = wm * 32 + mt * 16 + (lane & 15);
        int k = (lane >> 4) * 8;
        aAddr[mt] = (uint32_t)__cvta_generic_to_shared(sA + row * STRIDE + k);
    }
    uint32_t bAddr[2];
    #pragma unroll
    for (int ntp = 0; ntp < 2; ntp++) {
        int n = wn * 32 + ntp * 16 + ((lane >> 4) & 1) * 8 + (lane & 7);
        int k = ((lane >> 3) & 1) * 8;
        bAddr[ntp] = (uint32_t)__cvta_generic_to_shared(sB + n * STRIDE + k);
    }

    // ---- Mainloop: 8 k-steps of k16
    #pragma unroll
    for (int ks = 0; ks < 8; ks++) {
        uint32_t a[2][4];
        #pragma unroll
        for (int mt = 0; mt < 2; mt++)
            asm volatile("ldmatrix.sync.aligned.m8n8.x4.shared.b16 {%0,%1,%2,%3}, [%4];"
                : "=r"(a[mt][0]), "=r"(a[mt][1]), "=r"(a[mt][2]), "=r"(a[mt][3])
                : "r"(aAddr[mt] + ks * 32));
        uint32_t b[4][2];
        #pragma unroll
        for (int ntp = 0; ntp < 2; ntp++)
            asm volatile("ldmatrix.sync.aligned.m8n8.x4.shared.b16 {%0,%1,%2,%3}, [%4];"
                : "=r"(b[2*ntp][0]), "=r"(b[2*ntp][1]),
                  "=r"(b[2*ntp+1][0]), "=r"(b[2*ntp+1][1])
                : "r"(bAddr[ntp] + ks * 32));
        #pragma unroll
        for (int mt = 0; mt < 2; mt++)
            #pragma unroll
            for (int nt = 0; nt < 4; nt++)
                asm volatile(
                    "mma.sync.aligned.m16n8k16.row.col.f32.bf16.bf16.f32 "
                    "{%0,%1,%2,%3}, {%4,%5,%6,%7}, {%8,%9}, {%0,%1,%2,%3};"
                    : "+f"(acc[mt][nt][0]), "+f"(acc[mt][nt][1]),
                      "+f"(acc[mt][nt][2]), "+f"(acc[mt][nt][3])
                    : "r"(a[mt][0]), "r"(a[mt][1]), "r"(a[mt][2]), "r"(a[mt][3]),
                      "r"(b[nt][0]), "r"(b[nt][1]));
    }

    if (diag) epilogue<true >(acc, rowBase, colBase, wm, wn, lane);
    else      epilogue<false>(acc, rowBase, colBase, wm, wn, lane);

    // ---- Ticket: last CTA computes the scalar loss (fast log2)
    __shared__ bool is_last;
    __syncthreads();
    if (tid == 0) {
        __threadfence();
        unsigned int tk = atomicInc(&g_ticket, 0xFFFFFFFFu);
        is_last = (tk == (unsigned int)(gridDim.x - 1));
    }
    __syncthreads();
    if (is_last) {
        __threadfence();
        float acc2 = 0.0f;
        #pragma unroll 4
        for (int i = tid; i < TWO_N; i += 512)
            acc2 += __log2f(__ldcg(&g_rowsum[i])) * LN2F - g_pos[i] * INV_T;
        #pragma unroll
        for (int o = 16; o > 0; o >>= 1)
            acc2 += __shfl_xor_sync(0xFFFFFFFFu, acc2, o);
        __shared__ float sred[16];
        if ((tid & 31) == 0) sred[tid >> 5] = acc2;
        __syncthreads();
        if (tid == 0) {
            float tot = 0.0f;
            #pragma unroll
            for (int w = 0; w < 16; w++) tot += sred[w];
            out[0] = tot * (1.0f / (float)TWO_N);
        }
    }
}

// ---------------------------------------------------------------------------
extern "C" void kernel_launch(void* const* d_in, const int* in_sizes, int n_in,
                              void* d_out, int out_size) {
    const float* z1 = (const float*)d_in[0];
    const float* z2 = (const float*)d_in[1];

    cudaFuncSetAttribute(simgemm_kernel,
                         cudaFuncAttributeMaxDynamicSharedMemorySize, SMEM_SZ);

    normalize_pos_kernel<<<TWO_N / 2, 128>>>(z1, z2);
    simgemm_kernel<<<NUM_TILES, 512, SMEM_SZ>>>((float*)d_out);
}

// round 8
// speedup vs baseline: 1.3951x; 1.1975x over previous
#include <cuda_runtime.h>
#include <cuda_bf16.h>
#include <cstdint>

// NT-Xent fused: N=4096, Z=128, T=0.5
#define TWO_N 8192
#define ZD 128
#define INV_T 2.0f
// exp(sim/T) = 2^(sim * INV_T * log2(e)) ; fold sqrt of that scale into each
// stored bf16 row so the MMA accumulator is directly the ex2 argument.
#define SQRT_EXP_SCALE 1.6986435651438231f   // sqrt(INV_T * log2(e))
#define LN2F 0.6931471805599453f

#define BM 128
#define BN 128
#define ROW_TILES (TWO_N / BM)                       // 64
#define NUM_TILES (ROW_TILES * (ROW_TILES + 1) / 2)  // 2080 (upper triangle)
#define NUM_CTAS 304                     // persistent: 2 per SM x 152 SMs
#define STRIDE 136                       // bf16 elems per smem row (128 + 8 pad)
#define TILE_ELEMS (BM * STRIDE)         // 17408
#define TILE_BYTES (TILE_ELEMS * 2)      // 34816
#define SMEM_SZ (3 * TILE_BYTES)         // A + B0 + B1 = 104448

// Scratch (device globals — no allocation allowed)
__device__ __nv_bfloat16 g_nrep_bf16[TWO_N * ZD];
__device__ float         g_rowsum  [TWO_N];
__device__ float         g_pos     [TWO_N];
__device__ unsigned int  g_ticket;

// ---------------------------------------------------------------------------
// Kernel 1: normalize both rows of each positive pair (j, j+N) in one block;
// emit pre-scaled bf16 rows, fp32 positives, zero rowsums. 4096 blocks x 128.
// ---------------------------------------------------------------------------
__global__ void normalize_pos_kernel(const float* __restrict__ z1,
                                     const float* __restrict__ z2) {
    int j = blockIdx.x;                      // 0..4095
    int t = threadIdx.x;
    float v = z1[(size_t)j * ZD + t];
    float p = z2[(size_t)j * ZD + t];
    float s0 = v * v, s1 = p * p, s2 = v * p;
    #pragma unroll
    for (int o = 16; o > 0; o >>= 1) {
        s0 += __shfl_xor_sync(0xFFFFFFFFu, s0, o);
        s1 += __shfl_xor_sync(0xFFFFFFFFu, s1, o);
        s2 += __shfl_xor_sync(0xFFFFFFFFu, s2, o);
    }
    __shared__ float ws[4][3];
    int lane = t & 31, wid = t >> 5;
    if (lane == 0) { ws[wid][0] = s0; ws[wid][1] = s1; ws[wid][2] = s2; }
    __syncthreads();
    float n0 = ws[0][0] + ws[1][0] + ws[2][0] + ws[3][0];
    float n1 = ws[0][1] + ws[1][1] + ws[2][1] + ws[3][1];
    float dp = ws[0][2] + ws[1][2] + ws[2][2] + ws[3][2];
    float invA = 1.0f / fmaxf(sqrtf(n0), 1e-8f);
    float invB = 1.0f / fmaxf(sqrtf(n1), 1e-8f);
    g_nrep_bf16[(size_t)j * ZD + t] =
        __float2bfloat16(v * (invA * SQRT_EXP_SCALE));
    g_nrep_bf16[(size_t)(j + TWO_N/2) * ZD + t] =
        __float2bfloat16(p * (invB * SQRT_EXP_SCALE));
    if (t == 0) {
        float pos = dp * invA * invB;
        g_pos[j] = pos;
        g_pos[j + TWO_N/2] = pos;
        g_rowsum[j] = 0.0f;
        g_rowsum[j + TWO_N/2] = 0.0f;
        if (j == 0) g_ticket = 0u;
    }
}

// ---------------------------------------------------------------------------
// cp.async a full 128x128 bf16 tile (row strip rowBase) into padded smem
// ---------------------------------------------------------------------------
__device__ __forceinline__ void load_tile(__nv_bfloat16* dst, int rowBase, int tid) {
    #pragma unroll
    for (int it = 0; it < 4; it++) {
        int i2 = it * 512 + tid;          // 2048 16B-chunks per tile
        int rr = i2 >> 4, c = i2 & 15;
        uint32_t d = (uint32_t)__cvta_generic_to_shared(dst + rr * STRIDE + c * 8);
        const void* g = g_nrep_bf16 + (size_t)(rowBase + rr) * ZD + c * 8;
        asm volatile("cp.async.cg.shared.global [%0], [%1], 16;" :: "r"(d), "l"(g));
    }
}

// ---------------------------------------------------------------------------
// Epilogue (templated on DIAG): ex = ex2(acc) (scale pre-folded), optional
// self-diag mask; row sums always, column sums (symmetry) for off-diag tiles.
// ---------------------------------------------------------------------------
template<bool DIAG>
__device__ __forceinline__ void epilogue(float (&acc)[2][4][4], int rowBase,
                                         int colBase, int wm, int wn, int lane) {
    int g = lane >> 2, t = lane & 3;

    float colacc[8];
    #pragma unroll
    for (int c = 0; c < 8; c++) colacc[c] = 0.0f;

    #pragma unroll
    for (int mt = 0; mt < 2; mt++) {
        #pragma unroll
        for (int half = 0; half < 2; half++) {
            int i = rowBase + wm * 32 + mt * 16 + half * 8 + g;
            float s = 0.0f;
            #pragma unroll
            for (int nt = 0; nt < 4; nt++) {
                #pragma unroll
                for (int e = 0; e < 2; e++) {
                    float ex;
                    asm("ex2.approx.f32 %0, %1;" : "=f"(ex)
                        : "f"(acc[mt][nt][half * 2 + e]));
                    if (DIAG) {
                        int j = colBase + wn * 32 + t * 2 + nt * 8 + e;
                        if (i == j) ex = 0.0f;
                    }
                    s += ex;
                    colacc[nt * 2 + e] += ex;
                }
            }
            s += __shfl_xor_sync(0xFFFFFFFFu, s, 1);
            s += __shfl_xor_sync(0xFFFFFFFFu, s, 2);
            if (t == 0) atomicAdd(&g_rowsum[i], s);
        }
    }

    if (!DIAG) {
        #pragma unroll
        for (int c = 0; c < 8; c++) {
            float v = colacc[c];
            v += __shfl_xor_sync(0xFFFFFFFFu, v, 4);
            v += __shfl_xor_sync(0xFFFFFFFFu, v, 8);
            v += __shfl_xor_sync(0xFFFFFFFFu, v, 16);
            colacc[c] = v;
        }
        if (g == 0) {
            int jbase = colBase + wn * 32 + t * 2;
            #pragma unroll
            for (int c = 0; c < 8; c++) {
                int j = jbase + (c >> 1) * 8 + (c & 1);
                atomicAdd(&g_rowsum[j], colacc[c]);
            }
        }
    }
}

// ---------------------------------------------------------------------------
// Kernel 2: PERSISTENT fused sim GEMM. 304 CTAs; each owns a contiguous chunk
// of the row-major upper triangle. B double-buffered: next tile's B prefetched
// (cp.async) before the current mainloop, landing during compute. A reloaded
// only on row transitions. 512 threads = 16 warps (4m x 4n), 32x32 warp tile.
// ---------------------------------------------------------------------------
__global__ void __launch_bounds__(512, 2) simgemm_kernel(float* __restrict__ out) {
    extern __shared__ __nv_bfloat16 smem[];
    __nv_bfloat16* sA = smem;
    __nv_bfloat16* sB = smem + TILE_ELEMS;      // B0; B1 at +TILE_ELEMS

    int tid = threadIdx.x;
    int wid = tid >> 5, lane = tid & 31;

    // Contiguous chunk of the row-major triangle
    const int base = NUM_TILES / NUM_CTAS;      // 6
    const int rem  = NUM_TILES % NUM_CTAS;      // 256
    int bidx = blockIdx.x;
    int start = bidx * base + (bidx < rem ? bidx : rem);
    int count = base + (bidx < rem ? 1 : 0);

    // Decode (ty, tx) for start (row ty holds tiles tx in [ty, 64))
    int ty = 0, f = 0;
    while (f + (ROW_TILES - ty) <= start) { f += ROW_TILES - ty; ty++; }
    int tx = ty + (start - f);

    // Initial loads: A(ty) + B(tx) as one group
    load_tile(sA, ty * BM, tid);
    load_tile(sB, tx * BN, tid);
    asm volatile("cp.async.commit_group;" ::: "memory");

    int wm = wid & 3;        // warp row (4)
    int wn = wid >> 2;       // warp col (4)

    // ldmatrix base addresses (per lane)
    uint32_t aAddr[2];
    #pragma unroll
    for (int mt = 0; mt < 2; mt++) {
        int row = wm * 32 + mt * 16 + (lane & 15);
        int k = (lane >> 4) * 8;
        aAddr[mt] = (uint32_t)__cvta_generic_to_shared(sA + row * STRIDE + k);
    }
    uint32_t bAddr[2];
    #pragma unroll
    for (int ntp = 0; ntp < 2; ntp++) {
        int n = wn * 32 + ntp * 16 + ((lane >> 4) & 1) * 8 + (lane & 7);
        int k = ((lane >> 3) & 1) * 8;
        bAddr[ntp] = (uint32_t)__cvta_generic_to_shared(sB + n * STRIDE + k);
    }

    #pragma unroll 1
    for (int t = 0; t < count; t++) {
        uint32_t bOff = (uint32_t)(t & 1) * TILE_BYTES;
        int nty = ty, ntx = tx + 1;
        if (ntx == ROW_TILES) { nty = ty + 1; ntx = nty; }
        bool more = (t + 1 < count);

        // Wait for this tile's data (prefetched last iteration -> nearly free)
        asm volatile("cp.async.wait_group 0;" ::: "memory");
        __syncthreads();

        // Prefetch next tile's B into the alternate buffer; overlaps mainloop
        if (more) {
            load_tile(sB + ((t + 1) & 1) * TILE_ELEMS, ntx * BN, tid);
            asm volatile("cp.async.commit_group;" ::: "memory");
        }

        float acc[2][4][4];
        #pragma unroll
        for (int mt = 0; mt < 2; mt++)
            #pragma unroll
            for (int nt = 0; nt < 4; nt++)
                #pragma unroll
                for (int e = 0; e < 4; e++) acc[mt][nt][e] = 0.0f;

        // ---- Mainloop: 8 k-steps of k16
        #pragma unroll
        for (int ks = 0; ks < 8; ks++) {
            uint32_t a[2][4];
            #pragma unroll
            for (int mt = 0; mt < 2; mt++)
                asm volatile("ldmatrix.sync.aligned.m8n8.x4.shared.b16 {%0,%1,%2,%3}, [%4];"
                    : "=r"(a[mt][0]), "=r"(a[mt][1]), "=r"(a[mt][2]), "=r"(a[mt][3])
                    : "r"(aAddr[mt] + ks * 32));
            uint32_t b[4][2];
            #pragma unroll
            for (int ntp = 0; ntp < 2; ntp++)
                asm volatile("ldmatrix.sync.aligned.m8n8.x4.shared.b16 {%0,%1,%2,%3}, [%4];"
                    : "=r"(b[2*ntp][0]), "=r"(b[2*ntp][1]),
                      "=r"(b[2*ntp+1][0]), "=r"(b[2*ntp+1][1])
                    : "r"(bAddr[ntp] + bOff + ks * 32));
            #pragma unroll
            for (int mt = 0; mt < 2; mt++)
                #pragma unroll
                for (int nt = 0; nt < 4; nt++)
                    asm volatile(
                        "mma.sync.aligned.m16n8k16.row.col.f32.bf16.bf16.f32 "
                        "{%0,%1,%2,%3}, {%4,%5,%6,%7}, {%8,%9}, {%0,%1,%2,%3};"
                        : "+f"(acc[mt][nt][0]), "+f"(acc[mt][nt][1]),
                          "+f"(acc[mt][nt][2]), "+f"(acc[mt][nt][3])
                        : "r"(a[mt][0]), "r"(a[mt][1]), "r"(a[mt][2]), "r"(a[mt][3]),
                          "r"(b[nt][0]), "r"(b[nt][1]));
        }

        if (tx == ty) epilogue<true >(acc, ty * BM, tx * BN, wm, wn, lane);
        else          epilogue<false>(acc, ty * BM, tx * BN, wm, wn, lane);

        // Row transition: reload A (rare; bufA reuse needs all warps done)
        if (more && nty != ty) {
            __syncthreads();
            load_tile(sA, nty * BM, tid);
            asm volatile("cp.async.commit_group;" ::: "memory");
        }
        ty = nty; tx = ntx;
    }

    // ---- Ticket: last CTA computes the scalar loss (fast log2)
    __shared__ bool is_last;
    __syncthreads();
    if (tid == 0) {
        __threadfence();
        unsigned int tk = atomicInc(&g_ticket, 0xFFFFFFFFu);
        is_last = (tk == (unsigned int)(gridDim.x - 1));
    }
    __syncthreads();
    if (is_last) {
        __threadfence();
        float acc2 = 0.0f;
        #pragma unroll 4
        for (int i = tid; i < TWO_N; i += 512)
            acc2 += __log2f(__ldcg(&g_rowsum[i])) * LN2F - g_pos[i] * INV_T;
        #pragma unroll
        for (int o = 16; o > 0; o >>= 1)
            acc2 += __shfl_xor_sync(0xFFFFFFFFu, acc2, o);
        __shared__ float sred[16];
        if ((tid & 31) == 0) sred[tid >> 5] = acc2;
        __syncthreads();
        if (tid == 0) {
            float tot = 0.0f;
            #pragma unroll
            for (int w = 0; w < 16; w++) tot += sred[w];
            out[0] = tot * (1.0f / (float)TWO_N);
        }
    }
}

// ---------------------------------------------------------------------------
extern "C" void kernel_launch(void* const* d_in, const int* in_sizes, int n_in,
                              void* d_out, int out_size) {
    const float* z1 = (const float*)d_in[0];
    const float* z2 = (const float*)d_in[1];

    cudaFuncSetAttribute(simgemm_kernel,
                         cudaFuncAttributeMaxDynamicSharedMemorySize, SMEM_SZ);

    normalize_pos_kernel<<<TWO_N / 2, 128>>>(z1, z2);
    simgemm_kernel<<<NUM_CTAS, 512, SMEM_SZ>>>((float*)d_out);
}